// round 9
// baseline (speedup 1.0000x reference)
#include <cuda_runtime.h>

// ============================================================================
// GCN: 3-layer, N~100k, E~1.6M, D=H=128, C=64, fp32.
// R8 change (gemm only; rest = 456.7us passing kernel):
//  - k-unroll-by-4: x loaded as float4 over k (1 LDS.128 per row per 4 k-steps
//    instead of 4 LDS.32) -> x crossbar cost 4x lower.
//  - TM 4->8 (BM=64, 128 threads): W LDS amortized over 2x FMAs.
//    Per warp per k: ~10 crossbar wavefronts vs 64 FMA SMSP-cycles ->
//    FMA-bound (was crossbar-bound 12:8; measured L1=66.6% fma=46.1%).
// ============================================================================

#define MAX_N 131072
#define MAX_E 2097152
#define NB_MAX 256

__device__ float g_bufA[(size_t)MAX_N * 128];
__device__ float g_bufB[(size_t)MAX_N * 128];
__device__ float g_dinv[MAX_N];
__device__ int   g_rowptr[MAX_N + 1];
__device__ int   g_cursor[MAX_N + 1];
__device__ int   g_col[MAX_E];
__device__ int   g_blkSum[NB_MAX];
__device__ int   g_is64;

// ---------------------------------------------------------------------------
// dtype sniffer: int64 indices < 2^17 => every odd 32-bit word is 0.
// ---------------------------------------------------------------------------
__global__ void detect_kernel(const unsigned* __restrict__ words, int nwords) {
    __shared__ int any;
    if (threadIdx.x == 0) any = 0;
    __syncthreads();
    int found = 0;
    for (int i = threadIdx.x; 2 * i + 1 < nwords; i += blockDim.x) {
        if (words[2 * i + 1] != 0u) { found = 1; break; }
    }
    if (found) atomicOr(&any, 1);
    __syncthreads();
    if (threadIdx.x == 0) g_is64 = any ? 0 : 1;
}

__global__ void zero_kernel(int n) {
    int i = blockIdx.x * blockDim.x + threadIdx.x;
    if (i < n) g_cursor[i] = 0;
}

__global__ void count_kernel(const void* __restrict__ edges, int E) {
    int e = blockIdx.x * blockDim.x + threadIdx.x;
    if (e >= E) return;
    int dst;
    if (g_is64) dst = (int)((const long long*)edges)[E + e];
    else        dst = ((const int*)edges)[E + e];
    atomicAdd(&g_cursor[dst], 1);
}

// ---------------------------------------------------------------------------
// 3-phase exclusive scan of g_cursor[0..N) -> rowptr/cursor, plus dinv.
// ---------------------------------------------------------------------------
__global__ void __launch_bounds__(1024) scanA_kernel(int N) {
    __shared__ int sh[1024];
    int i = blockIdx.x * 1024 + threadIdx.x;
    sh[threadIdx.x] = (i < N) ? g_cursor[i] : 0;
    __syncthreads();
    #pragma unroll
    for (int off = 512; off > 0; off >>= 1) {
        if (threadIdx.x < off) sh[threadIdx.x] += sh[threadIdx.x + off];
        __syncthreads();
    }
    if (threadIdx.x == 0) g_blkSum[blockIdx.x] = sh[0];
}

__global__ void __launch_bounds__(NB_MAX) scanB_kernel(int nb) {
    __shared__ int sh[NB_MAX];
    int t = threadIdx.x;
    int v = (t < nb) ? g_blkSum[t] : 0;
    sh[t] = v;
    __syncthreads();
    #pragma unroll
    for (int off = 1; off < NB_MAX; off <<= 1) {
        int u = (t >= off) ? sh[t - off] : 0;
        __syncthreads();
        sh[t] += u;
        __syncthreads();
    }
    if (t < nb) g_blkSum[t] = sh[t] - v;   // exclusive
}

__global__ void __launch_bounds__(1024) scanC_kernel(int N) {
    __shared__ int sh[1024];
    int t = threadIdx.x;
    int i = blockIdx.x * 1024 + t;
    int c = (i < N) ? g_cursor[i] : 0;
    sh[t] = c;
    __syncthreads();
    for (int off = 1; off < 1024; off <<= 1) {
        int u = (t >= off) ? sh[t - off] : 0;
        __syncthreads();
        sh[t] += u;
        __syncthreads();
    }
    int excl = sh[t] - c + g_blkSum[blockIdx.x];
    if (i <= N) {
        g_rowptr[i] = excl;
        if (i < N) {
            g_cursor[i] = excl;
            g_dinv[i] = rsqrtf((float)(c + 1));   // +1 self loop
        }
    }
}

__global__ void fill_kernel(const void* __restrict__ edges, int E) {
    int e = blockIdx.x * blockDim.x + threadIdx.x;
    if (e >= E) return;
    int src, dst;
    if (g_is64) {
        src = (int)((const long long*)edges)[e];
        dst = (int)((const long long*)edges)[E + e];
    } else {
        src = ((const int*)edges)[e];
        dst = ((const int*)edges)[E + e];
    }
    int pos = atomicAdd(&g_cursor[dst], 1);
    g_col[pos] = src;
}

// ---------------------------------------------------------------------------
// GEMM: Y[N,K] = X[N,D] @ W[D,K], D=128, K in {128,64}.
// BM=64 rows, 128 threads as 8(tr) x 16(tc). Thread: rows tr*8..+7;
// cols {4tc..4tc+3} and (K=128) {64+4tc..64+4tc+3}.
// Mainloop processes 4 k per iteration: x rows loaded as float4 (LDS.128,
// 2 distinct addrs/warp = 1 wavefront each); W LDS.128 lane-contiguous.
// ---------------------------------------------------------------------------
template <int D, int K>
__global__ void __launch_bounds__(128) gemm_kernel(
    const float* __restrict__ X, const float* __restrict__ W,
    float* __restrict__ Y, int N)
{
    constexpr int BM = 64;
    constexpr int TM = 8;
    constexpr int NA = (K == 128) ? 4 : 2;  // packed accums per row
    constexpr int XP = D + 4;               // padded X row stride (floats)
    extern __shared__ float sm[];
    float* ws = sm;                          // [D][K]
    float* xs = sm + D * K;                  // [BM][XP]

    const int tid = threadIdx.x;
    const int row0 = blockIdx.x * BM;

    // Load W (row-major [k][c]) -- float4 vectorized.
    {
        const float4* Wv = (const float4*)W;
        float4* wv = (float4*)ws;
        for (int i = tid; i < D * K / 4; i += 128) wv[i] = Wv[i];
    }
    // Load X tile row-major: float4 loads -> float4 stores (conflict-free).
    {
        for (int i = tid; i < BM * (D / 4); i += 128) {
            int r  = i >> 5;            // D/4 = 32
            int k4 = i & 31;
            int gr = row0 + r;
            float4 v = make_float4(0.f, 0.f, 0.f, 0.f);
            if (gr < N) v = __ldcs((const float4*)(X + (size_t)gr * D) + k4);
            *(float4*)(xs + r * XP + k4 * 4) = v;
        }
    }
    __syncthreads();

    const int tc = tid & 15;
    const int tr = tid >> 4;                 // 0..7
    const int r0 = tr * TM;

    unsigned long long acc2[TM][NA];
    #pragma unroll
    for (int i = 0; i < TM; i++)
        #pragma unroll
        for (int j = 0; j < NA; j++) acc2[i][j] = 0ull;

    const ulonglong2* wsv = (const ulonglong2*)ws;   // [k][K/4] 16B units
    const float* xbase = xs + r0 * XP;

    #pragma unroll 2
    for (int kk = 0; kk < D; kk += 4) {
        float4 xq[TM];
        #pragma unroll
        for (int m = 0; m < TM; m++)
            xq[m] = *(const float4*)(xbase + m * XP + kk);

        #pragma unroll
        for (int dk = 0; dk < 4; dk++) {
            const int k = kk + dk;
            ulonglong2 wa = wsv[k * (K / 4) + tc];
            ulonglong2 wb;
            if (K == 128) wb = wsv[k * (K / 4) + 16 + tc];
            #pragma unroll
            for (int m = 0; m < TM; m++) {
                float xv = (dk == 0) ? xq[m].x : (dk == 1) ? xq[m].y
                         : (dk == 2) ? xq[m].z : xq[m].w;
                unsigned long long x2;
                asm("mov.b64 %0, {%1, %1};" : "=l"(x2) : "f"(xv));
                asm("fma.rn.f32x2 %0, %1, %2, %0;"
                    : "+l"(acc2[m][0]) : "l"(x2), "l"(wa.x));
                asm("fma.rn.f32x2 %0, %1, %2, %0;"
                    : "+l"(acc2[m][1]) : "l"(x2), "l"(wa.y));
                if (K == 128) {
                    asm("fma.rn.f32x2 %0, %1, %2, %0;"
                        : "+l"(acc2[m][NA - 2]) : "l"(x2), "l"(wb.x));
                    asm("fma.rn.f32x2 %0, %1, %2, %0;"
                        : "+l"(acc2[m][NA - 1]) : "l"(x2), "l"(wb.y));
                }
            }
        }
    }

    // Epilogue: per row, float4 at col 4tc and (K=128) float4 at col 64+4tc.
    #pragma unroll
    for (int m = 0; m < TM; m++) {
        int gr = row0 + r0 + m;
        if (gr < N) {
            float* yr = Y + (size_t)gr * K;
            float a, b, c, d;
            asm("mov.b64 {%0, %1}, %2;" : "=f"(a), "=f"(b) : "l"(acc2[m][0]));
            asm("mov.b64 {%0, %1}, %2;" : "=f"(c), "=f"(d) : "l"(acc2[m][1]));
            *(float4*)(yr + 4 * tc) = make_float4(a, b, c, d);
            if (K == 128) {
                asm("mov.b64 {%0, %1}, %2;" : "=f"(a), "=f"(b) : "l"(acc2[m][NA - 2]));
                asm("mov.b64 {%0, %1}, %2;" : "=f"(c), "=f"(d) : "l"(acc2[m][NA - 1]));
                *(float4*)(yr + 64 + 4 * tc) = make_float4(a, b, c, d);
            }
        }
    }
}

// ---------------------------------------------------------------------------
// Aggregation: one warp per node, pull over CSR in-edges, + self loop + bias.
// Streaming (__stcs) output stores keep gathered H buffer L2-resident.
// ---------------------------------------------------------------------------
__device__ __forceinline__ void loadv(const float* p, float (&v)[4]) {
    float4 t = *(const float4*)p; v[0] = t.x; v[1] = t.y; v[2] = t.z; v[3] = t.w;
}
__device__ __forceinline__ void loadv(const float* p, float (&v)[2]) {
    float2 t = *(const float2*)p; v[0] = t.x; v[1] = t.y;
}
__device__ __forceinline__ void storecs(float* p, const float (&v)[4]) {
    __stcs((float4*)p, make_float4(v[0], v[1], v[2], v[3]));
}
__device__ __forceinline__ void storecs(float* p, const float (&v)[2]) {
    __stcs((float2*)p, make_float2(v[0], v[1]));
}

template <int K, bool RELU>
__global__ void __launch_bounds__(256) aggregate_kernel(
    const float* __restrict__ H, const float* __restrict__ bias,
    float* __restrict__ out, int N)
{
    constexpr int VEC = K / 32;     // 4 (K=128) or 2 (K=64)
    int gw   = (int)((blockIdx.x * blockDim.x + threadIdx.x) >> 5);
    int lane = threadIdx.x & 31;
    if (gw >= N) return;

    const float di = g_dinv[gw];
    const int col0 = lane * VEC;

    float acc[VEC];
    {   // self loop: dinv[i]^2 * h[i]
        float v[VEC];
        loadv(H + (size_t)gw * K + col0, v);
        const float w = di * di;
        #pragma unroll
        for (int c = 0; c < VEC; c++) acc[c] = w * v[c];
    }

    int j = g_rowptr[gw];
    const int jend = g_rowptr[gw + 1];
    for (; j + 2 <= jend; j += 2) {
        int s0 = g_col[j], s1 = g_col[j + 1];
        float w0 = di * g_dinv[s0];
        float w1 = di * g_dinv[s1];
        float v0[VEC], v1[VEC];
        loadv(H + (size_t)s0 * K + col0, v0);
        loadv(H + (size_t)s1 * K + col0, v1);
        #pragma unroll
        for (int c = 0; c < VEC; c++) acc[c] = fmaf(w0, v0[c], acc[c]);
        #pragma unroll
        for (int c = 0; c < VEC; c++) acc[c] = fmaf(w1, v1[c], acc[c]);
    }
    if (j < jend) {
        int s0 = g_col[j];
        float w0 = di * g_dinv[s0];
        float v0[VEC];
        loadv(H + (size_t)s0 * K + col0, v0);
        #pragma unroll
        for (int c = 0; c < VEC; c++) acc[c] = fmaf(w0, v0[c], acc[c]);
    }

    float bv[VEC];
    loadv(bias + col0, bv);
    #pragma unroll
    for (int c = 0; c < VEC; c++) {
        acc[c] += bv[c];
        if (RELU) acc[c] = fmaxf(acc[c], 0.f);
    }
    storecs(out + (size_t)gw * K + col0, acc);
}

// ---------------------------------------------------------------------------
// Launch. Inputs (metadata order): x, edge_index, W0, b0, W1, b1, W2, b2.
// ---------------------------------------------------------------------------
extern "C" void kernel_launch(void* const* d_in, const int* in_sizes, int n_in,
                              void* d_out, int out_size) {
    const float* x     = (const float*)d_in[0];
    const void*  edges = d_in[1];
    const float* W0 = (const float*)d_in[2];
    const float* b0 = (const float*)d_in[3];
    const float* W1 = (const float*)d_in[4];
    const float* b1 = (const float*)d_in[5];
    const float* W2 = (const float*)d_in[6];
    const float* b2 = (const float*)d_in[7];
    float* out = (float*)d_out;

    const int H = in_sizes[3];            // 128
    const int C = in_sizes[7];            // 64
    const int D = in_sizes[2] / H;        // 128
    const int N = in_sizes[0] / D;        // 100000
    const int E = in_sizes[1] / 2;        // 1600000
    (void)n_in; (void)out_size;

    void *pA, *pB;
    cudaGetSymbolAddress(&pA, g_bufA);
    cudaGetSymbolAddress(&pB, g_bufB);
    float* bufA = (float*)pA;
    float* bufB = (float*)pB;

    const int smemHH = (D * H + 64 * (D + 4)) * (int)sizeof(float);  // ~97KB
    const int smemHC = (D * C + 64 * (D + 4)) * (int)sizeof(float);  // ~65KB
    cudaFuncSetAttribute(gemm_kernel<128, 128>,
                         cudaFuncAttributeMaxDynamicSharedMemorySize, smemHH);
    cudaFuncSetAttribute(gemm_kernel<128, 64>,
                         cudaFuncAttributeMaxDynamicSharedMemorySize, smemHC);

    const int gemmBlocks = (N + 63) / 64;
    const int aggBlocks  = (N + 7) / 8;     // 8 warps/block, 1 warp/node
    const int nb = (N + 1 + 1023) / 1024;

    // ---- CSR build interleaved with layer-0 GEMM (gemm0 = launch idx 3,
    //      the slot ncu profiles). Single stream => true deps preserved. ----
    int nwords = 2 * E < 4096 ? 2 * E : 4096;
    detect_kernel<<<1, 256>>>((const unsigned*)edges, nwords);          // 0
    zero_kernel<<<(N + 256) / 256, 256>>>(N + 1);                       // 1
    count_kernel<<<(E + 255) / 256, 256>>>(edges, E);                   // 2
    gemm_kernel<128, 128><<<gemmBlocks, 128, smemHH>>>(x, W0, bufA, N); // 3
    scanA_kernel<<<nb, 1024>>>(N);                                      // 4
    scanB_kernel<<<1, NB_MAX>>>(nb);                                    // 5
    scanC_kernel<<<nb, 1024>>>(N);                                      // 6
    fill_kernel<<<(E + 255) / 256, 256>>>(edges, E);                    // 7

    // ---- layer 0 aggregate + relu ----
    aggregate_kernel<128, true><<<aggBlocks, 256>>>(bufA, b0, bufB, N);

    // ---- layer 1 ----
    gemm_kernel<128, 128><<<gemmBlocks, 128, smemHH>>>(bufB, W1, bufA, N);
    aggregate_kernel<128, false><<<aggBlocks, 256>>>(bufA, b1, bufB, N);

    // ---- layer 2 ----
    gemm_kernel<128, 64><<<gemmBlocks, 128, smemHC>>>(bufB, W2, bufA, N);
    aggregate_kernel<64, false><<<aggBlocks, 256>>>(bufA, b2, out, N);
}

// round 10
// speedup vs baseline: 1.0470x; 1.0470x over previous
#include <cuda_runtime.h>

// ============================================================================
// GCN: 3-layer, N~100k, E~1.6M, D=H=128, C=64, fp32.
// R10 (gemm only; rest = 456.7us passing kernel):
//  - Recombine R8 (16 warps/SM occupancy) with R9 (low-crossbar float4-x
//    mainloop): BM=96, TM=6, 256 threads (16tc x 16tr), XP=D unpadded.
//    Per SM: crossbar 152 wf < FMA 192 cyc per k -> FMA-bound w/ margin.
//  - smem 112KB -> 2 blocks/SM; regs ~110.
// R9 lesson: TM=8@128thr cut L1 66.6->40.9% but occ 11.8% -> latency-bound.
// ============================================================================

#define MAX_N 131072
#define MAX_E 2097152
#define NB_MAX 256

__device__ float g_bufA[(size_t)MAX_N * 128];
__device__ float g_bufB[(size_t)MAX_N * 128];
__device__ float g_dinv[MAX_N];
__device__ int   g_rowptr[MAX_N + 1];
__device__ int   g_cursor[MAX_N + 1];
__device__ int   g_col[MAX_E];
__device__ int   g_blkSum[NB_MAX];
__device__ int   g_is64;

// ---------------------------------------------------------------------------
// dtype sniffer: int64 indices < 2^17 => every odd 32-bit word is 0.
// ---------------------------------------------------------------------------
__global__ void detect_kernel(const unsigned* __restrict__ words, int nwords) {
    __shared__ int any;
    if (threadIdx.x == 0) any = 0;
    __syncthreads();
    int found = 0;
    for (int i = threadIdx.x; 2 * i + 1 < nwords; i += blockDim.x) {
        if (words[2 * i + 1] != 0u) { found = 1; break; }
    }
    if (found) atomicOr(&any, 1);
    __syncthreads();
    if (threadIdx.x == 0) g_is64 = any ? 0 : 1;
}

__global__ void zero_kernel(int n) {
    int i = blockIdx.x * blockDim.x + threadIdx.x;
    if (i < n) g_cursor[i] = 0;
}

__global__ void count_kernel(const void* __restrict__ edges, int E) {
    int e = blockIdx.x * blockDim.x + threadIdx.x;
    if (e >= E) return;
    int dst;
    if (g_is64) dst = (int)((const long long*)edges)[E + e];
    else        dst = ((const int*)edges)[E + e];
    atomicAdd(&g_cursor[dst], 1);
}

// ---------------------------------------------------------------------------
// 3-phase exclusive scan of g_cursor[0..N) -> rowptr/cursor, plus dinv.
// ---------------------------------------------------------------------------
__global__ void __launch_bounds__(1024) scanA_kernel(int N) {
    __shared__ int sh[1024];
    int i = blockIdx.x * 1024 + threadIdx.x;
    sh[threadIdx.x] = (i < N) ? g_cursor[i] : 0;
    __syncthreads();
    #pragma unroll
    for (int off = 512; off > 0; off >>= 1) {
        if (threadIdx.x < off) sh[threadIdx.x] += sh[threadIdx.x + off];
        __syncthreads();
    }
    if (threadIdx.x == 0) g_blkSum[blockIdx.x] = sh[0];
}

__global__ void __launch_bounds__(NB_MAX) scanB_kernel(int nb) {
    __shared__ int sh[NB_MAX];
    int t = threadIdx.x;
    int v = (t < nb) ? g_blkSum[t] : 0;
    sh[t] = v;
    __syncthreads();
    #pragma unroll
    for (int off = 1; off < NB_MAX; off <<= 1) {
        int u = (t >= off) ? sh[t - off] : 0;
        __syncthreads();
        sh[t] += u;
        __syncthreads();
    }
    if (t < nb) g_blkSum[t] = sh[t] - v;   // exclusive
}

__global__ void __launch_bounds__(1024) scanC_kernel(int N) {
    __shared__ int sh[1024];
    int t = threadIdx.x;
    int i = blockIdx.x * 1024 + t;
    int c = (i < N) ? g_cursor[i] : 0;
    sh[t] = c;
    __syncthreads();
    for (int off = 1; off < 1024; off <<= 1) {
        int u = (t >= off) ? sh[t - off] : 0;
        __syncthreads();
        sh[t] += u;
        __syncthreads();
    }
    int excl = sh[t] - c + g_blkSum[blockIdx.x];
    if (i <= N) {
        g_rowptr[i] = excl;
        if (i < N) {
            g_cursor[i] = excl;
            g_dinv[i] = rsqrtf((float)(c + 1));   // +1 self loop
        }
    }
}

__global__ void fill_kernel(const void* __restrict__ edges, int E) {
    int e = blockIdx.x * blockDim.x + threadIdx.x;
    if (e >= E) return;
    int src, dst;
    if (g_is64) {
        src = (int)((const long long*)edges)[e];
        dst = (int)((const long long*)edges)[E + e];
    } else {
        src = ((const int*)edges)[e];
        dst = ((const int*)edges)[E + e];
    }
    int pos = atomicAdd(&g_cursor[dst], 1);
    g_col[pos] = src;
}

// ---------------------------------------------------------------------------
// GEMM: Y[N,K] = X[N,D] @ W[D,K], D=128, K in {128,64}.
// BM=96 rows, 256 threads as 16(tr) x 16(tc). Thread: rows tr*6..+5;
// cols {4tc..4tc+3} and (K=128) {64+4tc..64+4tc+3}.
// Mainloop: 4 k per iter; x rows loaded as float4 LDS.128 (2 distinct
// addrs/warp -> broadcast, 1 wf); W LDS.128 lane-contiguous.
// X in smem unpadded [r][D] -- all accesses float4-contiguous or broadcast.
// ---------------------------------------------------------------------------
template <int D, int K>
__global__ void __launch_bounds__(256) gemm_kernel(
    const float* __restrict__ X, const float* __restrict__ W,
    float* __restrict__ Y, int N)
{
    constexpr int BM = 96;
    constexpr int TM = 6;
    constexpr int NA = (K == 128) ? 4 : 2;  // packed accums per row
    extern __shared__ float sm[];
    float* ws = sm;                          // [D][K]
    float* xs = sm + D * K;                  // [BM][D]

    const int tid = threadIdx.x;
    const int row0 = blockIdx.x * BM;

    // Load W (row-major [k][c]) -- float4 vectorized.
    {
        const float4* Wv = (const float4*)W;
        float4* wv = (float4*)ws;
        for (int i = tid; i < D * K / 4; i += 256) wv[i] = Wv[i];
    }
    // Load X tile row-major: float4 loads -> contiguous float4 stores.
    {
        for (int i = tid; i < BM * (D / 4); i += 256) {
            int r  = i >> 5;            // D/4 = 32
            int k4 = i & 31;
            int gr = row0 + r;
            float4 v = make_float4(0.f, 0.f, 0.f, 0.f);
            if (gr < N) v = __ldcs((const float4*)(X + (size_t)gr * D) + k4);
            *(float4*)(xs + r * D + k4 * 4) = v;
        }
    }
    __syncthreads();

    const int tc = tid & 15;
    const int tr = tid >> 4;                 // 0..15
    const int r0 = tr * TM;

    unsigned long long acc2[TM][NA];
    #pragma unroll
    for (int i = 0; i < TM; i++)
        #pragma unroll
        for (int j = 0; j < NA; j++) acc2[i][j] = 0ull;

    const ulonglong2* wsv = (const ulonglong2*)ws;   // [k][K/4] 16B units
    const float* xbase = xs + r0 * D;

    #pragma unroll 2
    for (int kk = 0; kk < D; kk += 4) {
        float4 xq[TM];
        #pragma unroll
        for (int m = 0; m < TM; m++)
            xq[m] = *(const float4*)(xbase + m * D + kk);

        #pragma unroll
        for (int dk = 0; dk < 4; dk++) {
            const int k = kk + dk;
            ulonglong2 wa = wsv[k * (K / 4) + tc];
            ulonglong2 wb;
            if (K == 128) wb = wsv[k * (K / 4) + 16 + tc];
            #pragma unroll
            for (int m = 0; m < TM; m++) {
                float xv = (dk == 0) ? xq[m].x : (dk == 1) ? xq[m].y
                         : (dk == 2) ? xq[m].z : xq[m].w;
                unsigned long long x2;
                asm("mov.b64 %0, {%1, %1};" : "=l"(x2) : "f"(xv));
                asm("fma.rn.f32x2 %0, %1, %2, %0;"
                    : "+l"(acc2[m][0]) : "l"(x2), "l"(wa.x));
                asm("fma.rn.f32x2 %0, %1, %2, %0;"
                    : "+l"(acc2[m][1]) : "l"(x2), "l"(wa.y));
                if (K == 128) {
                    asm("fma.rn.f32x2 %0, %1, %2, %0;"
                        : "+l"(acc2[m][NA - 2]) : "l"(x2), "l"(wb.x));
                    asm("fma.rn.f32x2 %0, %1, %2, %0;"
                        : "+l"(acc2[m][NA - 1]) : "l"(x2), "l"(wb.y));
                }
            }
        }
    }

    // Epilogue: per row, float4 at col 4tc and (K=128) float4 at col 64+4tc.
    #pragma unroll
    for (int m = 0; m < TM; m++) {
        int gr = row0 + r0 + m;
        if (gr < N) {
            float* yr = Y + (size_t)gr * K;
            float a, b, c, d;
            asm("mov.b64 {%0, %1}, %2;" : "=f"(a), "=f"(b) : "l"(acc2[m][0]));
            asm("mov.b64 {%0, %1}, %2;" : "=f"(c), "=f"(d) : "l"(acc2[m][1]));
            *(float4*)(yr + 4 * tc) = make_float4(a, b, c, d);
            if (K == 128) {
                asm("mov.b64 {%0, %1}, %2;" : "=f"(a), "=f"(b) : "l"(acc2[m][NA - 2]));
                asm("mov.b64 {%0, %1}, %2;" : "=f"(c), "=f"(d) : "l"(acc2[m][NA - 1]));
                *(float4*)(yr + 64 + 4 * tc) = make_float4(a, b, c, d);
            }
        }
    }
}

// ---------------------------------------------------------------------------
// Aggregation: one warp per node, pull over CSR in-edges, + self loop + bias.
// Streaming (__stcs) output stores keep gathered H buffer L2-resident.
// ---------------------------------------------------------------------------
__device__ __forceinline__ void loadv(const float* p, float (&v)[4]) {
    float4 t = *(const float4*)p; v[0] = t.x; v[1] = t.y; v[2] = t.z; v[3] = t.w;
}
__device__ __forceinline__ void loadv(const float* p, float (&v)[2]) {
    float2 t = *(const float2*)p; v[0] = t.x; v[1] = t.y;
}
__device__ __forceinline__ void storecs(float* p, const float (&v)[4]) {
    __stcs((float4*)p, make_float4(v[0], v[1], v[2], v[3]));
}
__device__ __forceinline__ void storecs(float* p, const float (&v)[2]) {
    __stcs((float2*)p, make_float2(v[0], v[1]));
}

template <int K, bool RELU>
__global__ void __launch_bounds__(256) aggregate_kernel(
    const float* __restrict__ H, const float* __restrict__ bias,
    float* __restrict__ out, int N)
{
    constexpr int VEC = K / 32;     // 4 (K=128) or 2 (K=64)
    int gw   = (int)((blockIdx.x * blockDim.x + threadIdx.x) >> 5);
    int lane = threadIdx.x & 31;
    if (gw >= N) return;

    const float di = g_dinv[gw];
    const int col0 = lane * VEC;

    float acc[VEC];
    {   // self loop: dinv[i]^2 * h[i]
        float v[VEC];
        loadv(H + (size_t)gw * K + col0, v);
        const float w = di * di;
        #pragma unroll
        for (int c = 0; c < VEC; c++) acc[c] = w * v[c];
    }

    int j = g_rowptr[gw];
    const int jend = g_rowptr[gw + 1];
    for (; j + 2 <= jend; j += 2) {
        int s0 = g_col[j], s1 = g_col[j + 1];
        float w0 = di * g_dinv[s0];
        float w1 = di * g_dinv[s1];
        float v0[VEC], v1[VEC];
        loadv(H + (size_t)s0 * K + col0, v0);
        loadv(H + (size_t)s1 * K + col0, v1);
        #pragma unroll
        for (int c = 0; c < VEC; c++) acc[c] = fmaf(w0, v0[c], acc[c]);
        #pragma unroll
        for (int c = 0; c < VEC; c++) acc[c] = fmaf(w1, v1[c], acc[c]);
    }
    if (j < jend) {
        int s0 = g_col[j];
        float w0 = di * g_dinv[s0];
        float v0[VEC];
        loadv(H + (size_t)s0 * K + col0, v0);
        #pragma unroll
        for (int c = 0; c < VEC; c++) acc[c] = fmaf(w0, v0[c], acc[c]);
    }

    float bv[VEC];
    loadv(bias + col0, bv);
    #pragma unroll
    for (int c = 0; c < VEC; c++) {
        acc[c] += bv[c];
        if (RELU) acc[c] = fmaxf(acc[c], 0.f);
    }
    storecs(out + (size_t)gw * K + col0, acc);
}

// ---------------------------------------------------------------------------
// Launch. Inputs (metadata order): x, edge_index, W0, b0, W1, b1, W2, b2.
// ---------------------------------------------------------------------------
extern "C" void kernel_launch(void* const* d_in, const int* in_sizes, int n_in,
                              void* d_out, int out_size) {
    const float* x     = (const float*)d_in[0];
    const void*  edges = d_in[1];
    const float* W0 = (const float*)d_in[2];
    const float* b0 = (const float*)d_in[3];
    const float* W1 = (const float*)d_in[4];
    const float* b1 = (const float*)d_in[5];
    const float* W2 = (const float*)d_in[6];
    const float* b2 = (const float*)d_in[7];
    float* out = (float*)d_out;

    const int H = in_sizes[3];            // 128
    const int C = in_sizes[7];            // 64
    const int D = in_sizes[2] / H;        // 128
    const int N = in_sizes[0] / D;        // 100000
    const int E = in_sizes[1] / 2;        // 1600000
    (void)n_in; (void)out_size;

    void *pA, *pB;
    cudaGetSymbolAddress(&pA, g_bufA);
    cudaGetSymbolAddress(&pB, g_bufB);
    float* bufA = (float*)pA;
    float* bufB = (float*)pB;

    const int smemHH = (D * H + 96 * D) * (int)sizeof(float);   // 112KB
    const int smemHC = (D * C + 96 * D) * (int)sizeof(float);   // 80KB
    cudaFuncSetAttribute(gemm_kernel<128, 128>,
                         cudaFuncAttributeMaxDynamicSharedMemorySize, smemHH);
    cudaFuncSetAttribute(gemm_kernel<128, 64>,
                         cudaFuncAttributeMaxDynamicSharedMemorySize, smemHC);

    const int gemmBlocks = (N + 95) / 96;
    const int aggBlocks  = (N + 7) / 8;     // 8 warps/block, 1 warp/node
    const int nb = (N + 1 + 1023) / 1024;

    // ---- CSR build interleaved with layer-0 GEMM (gemm0 = launch idx 3,
    //      the slot ncu profiles). Single stream => true deps preserved. ----
    int nwords = 2 * E < 4096 ? 2 * E : 4096;
    detect_kernel<<<1, 256>>>((const unsigned*)edges, nwords);          // 0
    zero_kernel<<<(N + 256) / 256, 256>>>(N + 1);                       // 1
    count_kernel<<<(E + 255) / 256, 256>>>(edges, E);                   // 2
    gemm_kernel<128, 128><<<gemmBlocks, 256, smemHH>>>(x, W0, bufA, N); // 3
    scanA_kernel<<<nb, 1024>>>(N);                                      // 4
    scanB_kernel<<<1, NB_MAX>>>(nb);                                    // 5
    scanC_kernel<<<nb, 1024>>>(N);                                      // 6
    fill_kernel<<<(E + 255) / 256, 256>>>(edges, E);                    // 7

    // ---- layer 0 aggregate + relu ----
    aggregate_kernel<128, true><<<aggBlocks, 256>>>(bufA, b0, bufB, N);

    // ---- layer 1 ----
    gemm_kernel<128, 128><<<gemmBlocks, 256, smemHH>>>(bufB, W1, bufA, N);
    aggregate_kernel<128, false><<<aggBlocks, 256>>>(bufA, b1, bufB, N);

    // ---- layer 2 ----
    gemm_kernel<128, 64><<<gemmBlocks, 256, smemHC>>>(bufB, W2, bufA, N);
    aggregate_kernel<64, false><<<aggBlocks, 256>>>(bufA, b2, out, N);
}

// round 12
// speedup vs baseline: 1.0496x; 1.0025x over previous
#include <cuda_runtime.h>

// ============================================================================
// GCN: 3-layer, N~100k, E~1.6M, D=H=128, C=64, fp32.
// R12: byte-identical resubmit of R11 (R11 bench = broker infra failure, the
// 5th source-independent one; R4->R5 and R6/R7->R8 proved resubmission is
// the correct move). R11 = software-pipelined GEMM mainloop:
//  - W reads for k+1 prefetched while k computes (R10: L1=49.5% not binding,
//    fma=44.9%, issue=37.1% -> LDS->FMA short-scoreboard latency-bound).
//  - __launch_bounds__(256,2) pins 2 blocks/SM (regs ~114 must stay <=128).
//  - BM=96, TM=6, 16 warps/SM unchanged (R10-proven occupancy/crossbar mix).
// ============================================================================

#define MAX_N 131072
#define MAX_E 2097152
#define NB_MAX 256

__device__ float g_bufA[(size_t)MAX_N * 128];
__device__ float g_bufB[(size_t)MAX_N * 128];
__device__ float g_dinv[MAX_N];
__device__ int   g_rowptr[MAX_N + 1];
__device__ int   g_cursor[MAX_N + 1];
__device__ int   g_col[MAX_E];
__device__ int   g_blkSum[NB_MAX];
__device__ int   g_is64;

// ---------------------------------------------------------------------------
// dtype sniffer: int64 indices < 2^17 => every odd 32-bit word is 0.
// ---------------------------------------------------------------------------
__global__ void detect_kernel(const unsigned* __restrict__ words, int nwords) {
    __shared__ int any;
    if (threadIdx.x == 0) any = 0;
    __syncthreads();
    int found = 0;
    for (int i = threadIdx.x; 2 * i + 1 < nwords; i += blockDim.x) {
        if (words[2 * i + 1] != 0u) { found = 1; break; }
    }
    if (found) atomicOr(&any, 1);
    __syncthreads();
    if (threadIdx.x == 0) g_is64 = any ? 0 : 1;
}

__global__ void zero_kernel(int n) {
    int i = blockIdx.x * blockDim.x + threadIdx.x;
    if (i < n) g_cursor[i] = 0;
}

__global__ void count_kernel(const void* __restrict__ edges, int E) {
    int e = blockIdx.x * blockDim.x + threadIdx.x;
    if (e >= E) return;
    int dst;
    if (g_is64) dst = (int)((const long long*)edges)[E + e];
    else        dst = ((const int*)edges)[E + e];
    atomicAdd(&g_cursor[dst], 1);
}

// ---------------------------------------------------------------------------
// 3-phase exclusive scan of g_cursor[0..N) -> rowptr/cursor, plus dinv.
// ---------------------------------------------------------------------------
__global__ void __launch_bounds__(1024) scanA_kernel(int N) {
    __shared__ int sh[1024];
    int i = blockIdx.x * 1024 + threadIdx.x;
    sh[threadIdx.x] = (i < N) ? g_cursor[i] : 0;
    __syncthreads();
    #pragma unroll
    for (int off = 512; off > 0; off >>= 1) {
        if (threadIdx.x < off) sh[threadIdx.x] += sh[threadIdx.x + off];
        __syncthreads();
    }
    if (threadIdx.x == 0) g_blkSum[blockIdx.x] = sh[0];
}

__global__ void __launch_bounds__(NB_MAX) scanB_kernel(int nb) {
    __shared__ int sh[NB_MAX];
    int t = threadIdx.x;
    int v = (t < nb) ? g_blkSum[t] : 0;
    sh[t] = v;
    __syncthreads();
    #pragma unroll
    for (int off = 1; off < NB_MAX; off <<= 1) {
        int u = (t >= off) ? sh[t - off] : 0;
        __syncthreads();
        sh[t] += u;
        __syncthreads();
    }
    if (t < nb) g_blkSum[t] = sh[t] - v;   // exclusive
}

__global__ void __launch_bounds__(1024) scanC_kernel(int N) {
    __shared__ int sh[1024];
    int t = threadIdx.x;
    int i = blockIdx.x * 1024 + t;
    int c = (i < N) ? g_cursor[i] : 0;
    sh[t] = c;
    __syncthreads();
    for (int off = 1; off < 1024; off <<= 1) {
        int u = (t >= off) ? sh[t - off] : 0;
        __syncthreads();
        sh[t] += u;
        __syncthreads();
    }
    int excl = sh[t] - c + g_blkSum[blockIdx.x];
    if (i <= N) {
        g_rowptr[i] = excl;
        if (i < N) {
            g_cursor[i] = excl;
            g_dinv[i] = rsqrtf((float)(c + 1));   // +1 self loop
        }
    }
}

__global__ void fill_kernel(const void* __restrict__ edges, int E) {
    int e = blockIdx.x * blockDim.x + threadIdx.x;
    if (e >= E) return;
    int src, dst;
    if (g_is64) {
        src = (int)((const long long*)edges)[e];
        dst = (int)((const long long*)edges)[E + e];
    } else {
        src = ((const int*)edges)[e];
        dst = ((const int*)edges)[E + e];
    }
    int pos = atomicAdd(&g_cursor[dst], 1);
    g_col[pos] = src;
}

// ---------------------------------------------------------------------------
// GEMM: Y[N,K] = X[N,D] @ W[D,K], D=128, K in {128,64}.
// BM=96 rows, 256 threads as 16(tr) x 16(tc). Thread: rows tr*6..+5;
// cols {4tc..4tc+3} and (K=128) {64+4tc..64+4tc+3}.
// Mainloop: 4 k per iter; x rows loaded as float4 LDS.128 (broadcast, 1 wf);
// W LDS.128 lane-contiguous, SOFTWARE-PIPELINED one k ahead (wraparound
// prefetch (k+1)&(D-1) -- final extra load is harmless).
// ---------------------------------------------------------------------------
template <int D, int K>
__global__ void __launch_bounds__(256, 2) gemm_kernel(
    const float* __restrict__ X, const float* __restrict__ W,
    float* __restrict__ Y, int N)
{
    constexpr int BM = 96;
    constexpr int TM = 6;
    constexpr int NA = (K == 128) ? 4 : 2;  // packed accums per row
    extern __shared__ float sm[];
    float* ws = sm;                          // [D][K]
    float* xs = sm + D * K;                  // [BM][D]

    const int tid = threadIdx.x;
    const int row0 = blockIdx.x * BM;

    // Load W (row-major [k][c]) -- float4 vectorized.
    {
        const float4* Wv = (const float4*)W;
        float4* wv = (float4*)ws;
        for (int i = tid; i < D * K / 4; i += 256) wv[i] = Wv[i];
    }
    // Load X tile row-major: float4 loads -> contiguous float4 stores.
    {
        for (int i = tid; i < BM * (D / 4); i += 256) {
            int r  = i >> 5;            // D/4 = 32
            int k4 = i & 31;
            int gr = row0 + r;
            float4 v = make_float4(0.f, 0.f, 0.f, 0.f);
            if (gr < N) v = __ldcs((const float4*)(X + (size_t)gr * D) + k4);
            *(float4*)(xs + r * D + k4 * 4) = v;
        }
    }
    __syncthreads();

    const int tc = tid & 15;
    const int tr = tid >> 4;                 // 0..15
    const int r0 = tr * TM;

    unsigned long long acc2[TM][NA];
    #pragma unroll
    for (int i = 0; i < TM; i++)
        #pragma unroll
        for (int j = 0; j < NA; j++) acc2[i][j] = 0ull;

    const ulonglong2* wsv = (const ulonglong2*)ws;   // [k][K/4] 16B units
    const float* xbase = xs + r0 * D;

    // Prime the W pipeline with k=0.
    ulonglong2 wa = wsv[tc];
    ulonglong2 wb;
    if (K == 128) wb = wsv[16 + tc];

    #pragma unroll 2
    for (int kk = 0; kk < D; kk += 4) {
        float4 xq[TM];
        #pragma unroll
        for (int m = 0; m < TM; m++)
            xq[m] = *(const float4*)(xbase + m * D + kk);

        #pragma unroll
        for (int dk = 0; dk < 4; dk++) {
            // Prefetch W for k+1 (wraps to 0 at the end; harmless reload).
            const int kn = (kk + dk + 1) & (D - 1);
            ulonglong2 wa_n = wsv[kn * (K / 4) + tc];
            ulonglong2 wb_n;
            if (K == 128) wb_n = wsv[kn * (K / 4) + 16 + tc];

            #pragma unroll
            for (int m = 0; m < TM; m++) {
                float xv = (dk == 0) ? xq[m].x : (dk == 1) ? xq[m].y
                         : (dk == 2) ? xq[m].z : xq[m].w;
                unsigned long long x2;
                asm("mov.b64 %0, {%1, %1};" : "=l"(x2) : "f"(xv));
                asm("fma.rn.f32x2 %0, %1, %2, %0;"
                    : "+l"(acc2[m][0]) : "l"(x2), "l"(wa.x));
                asm("fma.rn.f32x2 %0, %1, %2, %0;"
                    : "+l"(acc2[m][1]) : "l"(x2), "l"(wa.y));
                if (K == 128) {
                    asm("fma.rn.f32x2 %0, %1, %2, %0;"
                        : "+l"(acc2[m][NA - 2]) : "l"(x2), "l"(wb.x));
                    asm("fma.rn.f32x2 %0, %1, %2, %0;"
                        : "+l"(acc2[m][NA - 1]) : "l"(x2), "l"(wb.y));
                }
            }
            wa = wa_n;
            if (K == 128) wb = wb_n;
        }
    }

    // Epilogue: per row, float4 at col 4tc and (K=128) float4 at col 64+4tc.
    #pragma unroll
    for (int m = 0; m < TM; m++) {
        int gr = row0 + r0 + m;
        if (gr < N) {
            float* yr = Y + (size_t)gr * K;
            float a, b, c, d;
            asm("mov.b64 {%0, %1}, %2;" : "=f"(a), "=f"(b) : "l"(acc2[m][0]));
            asm("mov.b64 {%0, %1}, %2;" : "=f"(c), "=f"(d) : "l"(acc2[m][1]));
            *(float4*)(yr + 4 * tc) = make_float4(a, b, c, d);
            if (K == 128) {
                asm("mov.b64 {%0, %1}, %2;" : "=f"(a), "=f"(b) : "l"(acc2[m][NA - 2]));
                asm("mov.b64 {%0, %1}, %2;" : "=f"(c), "=f"(d) : "l"(acc2[m][NA - 1]));
                *(float4*)(yr + 64 + 4 * tc) = make_float4(a, b, c, d);
            }
        }
    }
}

// ---------------------------------------------------------------------------
// Aggregation: one warp per node, pull over CSR in-edges, + self loop + bias.
// Streaming (__stcs) output stores keep gathered H buffer L2-resident.
// ---------------------------------------------------------------------------
__device__ __forceinline__ void loadv(const float* p, float (&v)[4]) {
    float4 t = *(const float4*)p; v[0] = t.x; v[1] = t.y; v[2] = t.z; v[3] = t.w;
}
__device__ __forceinline__ void loadv(const float* p, float (&v)[2]) {
    float2 t = *(const float2*)p; v[0] = t.x; v[1] = t.y;
}
__device__ __forceinline__ void storecs(float* p, const float (&v)[4]) {
    __stcs((float4*)p, make_float4(v[0], v[1], v[2], v[3]));
}
__device__ __forceinline__ void storecs(float* p, const float (&v)[2]) {
    __stcs((float2*)p, make_float2(v[0], v[1]));
}

template <int K, bool RELU>
__global__ void __launch_bounds__(256) aggregate_kernel(
    const float* __restrict__ H, const float* __restrict__ bias,
    float* __restrict__ out, int N)
{
    constexpr int VEC = K / 32;     // 4 (K=128) or 2 (K=64)
    int gw   = (int)((blockIdx.x * blockDim.x + threadIdx.x) >> 5);
    int lane = threadIdx.x & 31;
    if (gw >= N) return;

    const float di = g_dinv[gw];
    const int col0 = lane * VEC;

    float acc[VEC];
    {   // self loop: dinv[i]^2 * h[i]
        float v[VEC];
        loadv(H + (size_t)gw * K + col0, v);
        const float w = di * di;
        #pragma unroll
        for (int c = 0; c < VEC; c++) acc[c] = w * v[c];
    }

    int j = g_rowptr[gw];
    const int jend = g_rowptr[gw + 1];
    for (; j + 2 <= jend; j += 2) {
        int s0 = g_col[j], s1 = g_col[j + 1];
        float w0 = di * g_dinv[s0];
        float w1 = di * g_dinv[s1];
        float v0[VEC], v1[VEC];
        loadv(H + (size_t)s0 * K + col0, v0);
        loadv(H + (size_t)s1 * K + col0, v1);
        #pragma unroll
        for (int c = 0; c < VEC; c++) acc[c] = fmaf(w0, v0[c], acc[c]);
        #pragma unroll
        for (int c = 0; c < VEC; c++) acc[c] = fmaf(w1, v1[c], acc[c]);
    }
    if (j < jend) {
        int s0 = g_col[j];
        float w0 = di * g_dinv[s0];
        float v0[VEC];
        loadv(H + (size_t)s0 * K + col0, v0);
        #pragma unroll
        for (int c = 0; c < VEC; c++) acc[c] = fmaf(w0, v0[c], acc[c]);
    }

    float bv[VEC];
    loadv(bias + col0, bv);
    #pragma unroll
    for (int c = 0; c < VEC; c++) {
        acc[c] += bv[c];
        if (RELU) acc[c] = fmaxf(acc[c], 0.f);
    }
    storecs(out + (size_t)gw * K + col0, acc);
}

// ---------------------------------------------------------------------------
// Launch. Inputs (metadata order): x, edge_index, W0, b0, W1, b1, W2, b2.
// ---------------------------------------------------------------------------
extern "C" void kernel_launch(void* const* d_in, const int* in_sizes, int n_in,
                              void* d_out, int out_size) {
    const float* x     = (const float*)d_in[0];
    const void*  edges = d_in[1];
    const float* W0 = (const float*)d_in[2];
    const float* b0 = (const float*)d_in[3];
    const float* W1 = (const float*)d_in[4];
    const float* b1 = (const float*)d_in[5];
    const float* W2 = (const float*)d_in[6];
    const float* b2 = (const float*)d_in[7];
    float* out = (float*)d_out;

    const int H = in_sizes[3];            // 128
    const int C = in_sizes[7];            // 64
    const int D = in_sizes[2] / H;        // 128
    const int N = in_sizes[0] / D;        // 100000
    const int E = in_sizes[1] / 2;        // 1600000
    (void)n_in; (void)out_size;

    void *pA, *pB;
    cudaGetSymbolAddress(&pA, g_bufA);
    cudaGetSymbolAddress(&pB, g_bufB);
    float* bufA = (float*)pA;
    float* bufB = (float*)pB;

    const int smemHH = (D * H + 96 * D) * (int)sizeof(float);   // 112KB
    const int smemHC = (D * C + 96 * D) * (int)sizeof(float);   // 80KB
    cudaFuncSetAttribute(gemm_kernel<128, 128>,
                         cudaFuncAttributeMaxDynamicSharedMemorySize, smemHH);
    cudaFuncSetAttribute(gemm_kernel<128, 64>,
                         cudaFuncAttributeMaxDynamicSharedMemorySize, smemHC);

    const int gemmBlocks = (N + 95) / 96;
    const int aggBlocks  = (N + 7) / 8;     // 8 warps/block, 1 warp/node
    const int nb = (N + 1 + 1023) / 1024;

    // ---- CSR build interleaved with layer-0 GEMM (gemm0 = launch idx 3,
    //      the slot ncu profiles). Single stream => true deps preserved. ----
    int nwords = 2 * E < 4096 ? 2 * E : 4096;
    detect_kernel<<<1, 256>>>((const unsigned*)edges, nwords);          // 0
    zero_kernel<<<(N + 256) / 256, 256>>>(N + 1);                       // 1
    count_kernel<<<(E + 255) / 256, 256>>>(edges, E);                   // 2
    gemm_kernel<128, 128><<<gemmBlocks, 256, smemHH>>>(x, W0, bufA, N); // 3
    scanA_kernel<<<nb, 1024>>>(N);                                      // 4
    scanB_kernel<<<1, NB_MAX>>>(nb);                                    // 5
    scanC_kernel<<<nb, 1024>>>(N);                                      // 6
    fill_kernel<<<(E + 255) / 256, 256>>>(edges, E);                    // 7

    // ---- layer 0 aggregate + relu ----
    aggregate_kernel<128, true><<<aggBlocks, 256>>>(bufA, b0, bufB, N);

    // ---- layer 1 ----
    gemm_kernel<128, 128><<<gemmBlocks, 256, smemHH>>>(bufB, W1, bufA, N);
    aggregate_kernel<128, false><<<aggBlocks, 256>>>(bufA, b1, bufB, N);

    // ---- layer 2 ----
    gemm_kernel<128, 64><<<gemmBlocks, 256, smemHC>>>(bufB, W2, bufA, N);
    aggregate_kernel<64, false><<<aggBlocks, 256>>>(bufA, b2, out, N);
}